// round 7
// baseline (speedup 1.0000x reference)
#include <cuda_runtime.h>
#include <cstdint>

#define BD 4
#define CD 256
#define HD 56
#define WD 56
#define GD 16
#define GCD 16
#define POSN (BD*HD*WD)   // 12544
#define IN1 2112
#define OUT1 96
#define OWD 112

// Scratch (device globals: no cudaMalloc allowed)
__device__ float g_desc[(size_t)IN1 * POSN];   // [feature][pos]  ~106 MB
__device__ float g_r[(size_t)POSN * OUT1];     // [pos][96]       ~4.8 MB

// ---------------------------------------------------------------------------
// Scrambled-unfold tap semantics (matches the ACTUAL reference code):
//   for output pos (h2, w2), tap (kh, kw):
//     m = kw*56 + h2;  h = m/3;  j = m%3
//     T[gc][kh][kw] = x[b, c, h + kh - 1, w2 + j - 1]   (0 outside)
// ---------------------------------------------------------------------------
__device__ __forceinline__ void load_taps(const float* __restrict__ x,
                                          int b, int g, int h2,
                                          float (*xs)[3][3][58], int tid) {
    const unsigned cbase = (unsigned)(b*CD + g*GCD);
    for (int idx = tid; idx < GCD * 9 * 58; idx += 128) {
        int wp = idx % 58;
        int t  = idx / 58;          // [0,144)
        int kh = t % 3;
        int kw = (t / 3) % 3;
        int gc = t / 9;
        int m  = kw * 56 + h2;
        int hh = m / 3 + kh - 1;
        int ww = wp - 1;
        float v = 0.f;
        if (hh >= 0 && hh < HD && ww >= 0 && ww < WD)
            v = x[((cbase + gc)*HD + hh)*WD + ww];
        xs[gc][kw][kh][wp] = v;
    }
}

// ---------------------------------------------------------------------------
// K1: build descriptor  desc[feature][pos]
// ---------------------------------------------------------------------------
__global__ __launch_bounds__(128) void desc_kernel(const float* __restrict__ x) {
    const int g = blockIdx.x, h2 = blockIdx.y, b = blockIdx.z;
    __shared__ float xs[GCD][3][3][58];   // 33408 B

    const int tid = threadIdx.x;
    load_taps(x, b, g, h2, xs, tid);
    __syncthreads();

    const int jv0 = h2 % 3, jv1 = (56 + h2) % 3, jv2 = (112 + h2) % 3;
    const unsigned posBase = (unsigned)(b*HD + h2)*WD;

    // x2 / x3: items = (gc, w)
    for (int it = tid; it < GCD * WD; it += 128) {
        int w  = it % WD;
        int gc = it / WD;
        float T[3][3];
        #pragma unroll
        for (int kh = 0; kh < 3; kh++) {
            T[kh][0] = xs[gc][0][kh][w + jv0];
            T[kh][1] = xs[gc][1][kh][w + jv1];
            T[kh][2] = xs[gc][2][kh][w + jv2];
        }
        unsigned f2 = (unsigned)(576 + g*48 + gc*3);
        unsigned f3 = (unsigned)(1344 + g*48 + gc*3);
        #pragma unroll
        for (int kw = 0; kw < 3; kw++) {
            float m = fmaxf(T[0][kw], fmaxf(T[1][kw], T[2][kw]));   // max over kh
            g_desc[(f2 + kw)*POSN + posBase + w] = m;
        }
        #pragma unroll
        for (int kh = 0; kh < 3; kh++) {
            float m = fmaxf(T[kh][0], fmaxf(T[kh][1], T[kh][2]));   // max over kw
            g_desc[(f3 + kh)*POSN + posBase + w] = m;
        }
    }

    // x1: items = (jc, w), strided max over channels {jc, jc+4, jc+8, jc+12}
    const int jvv[3] = {jv0, jv1, jv2};
    for (int it = tid; it < 4 * WD; it += 128) {
        int w  = it % WD;
        int jc = it / WD;
        unsigned f1 = (unsigned)(g*36 + jc*9);
        #pragma unroll
        for (int kh = 0; kh < 3; kh++) {
            #pragma unroll
            for (int kw = 0; kw < 3; kw++) {
                int wp = w + jvv[kw];
                float m = xs[jc][kw][kh][wp];
                m = fmaxf(m, xs[jc + 4 ][kw][kh][wp]);
                m = fmaxf(m, xs[jc + 8 ][kw][kh][wp]);
                m = fmaxf(m, xs[jc + 12][kw][kh][wp]);
                g_desc[(f1 + kh*3 + kw)*POSN + posBase + w] = m;
            }
        }
    }
}

// ---------------------------------------------------------------------------
// K2: tensor-core TF32 GEMM (3xTF32 split) — unchanged from R6 (verified good)
// ---------------------------------------------------------------------------
#define GBM 128
#define GBK 16
#define APAD 136
#define BPAD 104

__device__ __forceinline__ uint32_t f2tf32(float f) {
    uint32_t r;
    asm("cvt.rna.tf32.f32 %0, %1;" : "=r"(r) : "f"(f));
    return r;
}

__device__ __forceinline__ void mma_tf32(float* c, const uint32_t* a, const uint32_t* b) {
    asm volatile(
        "mma.sync.aligned.m16n8k8.row.col.f32.tf32.tf32.f32 "
        "{%0,%1,%2,%3}, {%4,%5,%6,%7}, {%8,%9}, {%0,%1,%2,%3};"
        : "+f"(c[0]), "+f"(c[1]), "+f"(c[2]), "+f"(c[3])
        : "r"(a[0]), "r"(a[1]), "r"(a[2]), "r"(a[3]), "r"(b[0]), "r"(b[1]));
}

__global__ __launch_bounds__(256) void gemm_tc_kernel(
    const float* __restrict__ w1,
    const float* __restrict__ gamma, const float* __restrict__ beta,
    const float* __restrict__ mean,  const float* __restrict__ var)
{
    __shared__ float Ah[GBK][APAD], Al[GBK][APAD];
    __shared__ float Bh[GBK][BPAD], Bl[GBK][BPAD];

    const int tid  = threadIdx.x;
    const int warp = tid >> 5;
    const int lane = tid & 31;
    const int wm = warp & 3;
    const int wn = warp >> 2;
    const int ar = lane >> 2;
    const int ac = lane & 3;
    const unsigned row0 = blockIdx.x * GBM;

    float c[2][6][4];
    #pragma unroll
    for (int mt = 0; mt < 2; mt++)
        #pragma unroll
        for (int nt = 0; nt < 6; nt++)
            #pragma unroll
            for (int q = 0; q < 4; q++) c[mt][nt][q] = 0.f;

    for (int k0 = 0; k0 < IN1; k0 += GBK) {
        #pragma unroll
        for (int i = 0; i < 2; i++) {
            int idx4 = tid + (i << 8);
            int m4 = idx4 & 31;
            int k  = idx4 >> 5;
            float4 v = *reinterpret_cast<const float4*>(
                &g_desc[(unsigned)(k0 + k)*POSN + row0 + m4*4]);
            float* dh = &Ah[k][m4*4];
            float* dl = &Al[k][m4*4];
            float h0 = __uint_as_float(f2tf32(v.x)); dh[0]=h0; dl[0]=__uint_as_float(f2tf32(v.x-h0));
            float h1 = __uint_as_float(f2tf32(v.y)); dh[1]=h1; dl[1]=__uint_as_float(f2tf32(v.y-h1));
            float h2 = __uint_as_float(f2tf32(v.z)); dh[2]=h2; dl[2]=__uint_as_float(f2tf32(v.z-h2));
            float h3 = __uint_as_float(f2tf32(v.w)); dh[3]=h3; dl[3]=__uint_as_float(f2tf32(v.w-h3));
        }
        #pragma unroll
        for (int i = 0; i < 6; i++) {
            int idx = tid + (i << 8);
            int k = idx & 15;
            int n = idx >> 4;
            float v = w1[(unsigned)n*IN1 + k0 + k];
            float h = __uint_as_float(f2tf32(v));
            Bh[k][n] = h;
            Bl[k][n] = __uint_as_float(f2tf32(v - h));
        }
        __syncthreads();

        #pragma unroll
        for (int ks = 0; ks < 2; ks++) {
            const int kb = ks * 8;
            uint32_t ah[2][4], al[2][4];
            #pragma unroll
            for (int mt = 0; mt < 2; mt++) {
                int mrow = wm*32 + mt*16 + ar;
                ah[mt][0] = __float_as_uint(Ah[kb+ac  ][mrow  ]);
                ah[mt][1] = __float_as_uint(Ah[kb+ac  ][mrow+8]);
                ah[mt][2] = __float_as_uint(Ah[kb+ac+4][mrow  ]);
                ah[mt][3] = __float_as_uint(Ah[kb+ac+4][mrow+8]);
                al[mt][0] = __float_as_uint(Al[kb+ac  ][mrow  ]);
                al[mt][1] = __float_as_uint(Al[kb+ac  ][mrow+8]);
                al[mt][2] = __float_as_uint(Al[kb+ac+4][mrow  ]);
                al[mt][3] = __float_as_uint(Al[kb+ac+4][mrow+8]);
            }
            uint32_t bh[6][2], bl[6][2];
            #pragma unroll
            for (int nt = 0; nt < 6; nt++) {
                int n = wn*48 + nt*8 + ar;
                bh[nt][0] = __float_as_uint(Bh[kb+ac  ][n]);
                bh[nt][1] = __float_as_uint(Bh[kb+ac+4][n]);
                bl[nt][0] = __float_as_uint(Bl[kb+ac  ][n]);
                bl[nt][1] = __float_as_uint(Bl[kb+ac+4][n]);
            }
            #pragma unroll
            for (int mt = 0; mt < 2; mt++)
                #pragma unroll
                for (int nt = 0; nt < 6; nt++) {
                    mma_tf32(c[mt][nt], ah[mt], bl[nt]);
                    mma_tf32(c[mt][nt], al[mt], bh[nt]);
                    mma_tf32(c[mt][nt], ah[mt], bh[nt]);
                }
        }
        __syncthreads();
    }

    #pragma unroll
    for (int nt = 0; nt < 6; nt++) {
        int n0 = wn*48 + nt*8 + 2*ac;
        float s0 = gamma[n0  ] * rsqrtf(var[n0  ] + 1e-5f);
        float b0 = beta[n0  ] - mean[n0  ] * s0;
        float s1 = gamma[n0+1] * rsqrtf(var[n0+1] + 1e-5f);
        float b1 = beta[n0+1] - mean[n0+1] * s1;
        #pragma unroll
        for (int mt = 0; mt < 2; mt++) {
            unsigned m0 = row0 + wm*32 + mt*16 + ar;
            float2 v01 = { fmaxf(fmaf(c[mt][nt][0], s0, b0), 0.f),
                           fmaxf(fmaf(c[mt][nt][1], s1, b1), 0.f) };
            *reinterpret_cast<float2*>(&g_r[m0*OUT1 + n0]) = v01;
            float2 v23 = { fmaxf(fmaf(c[mt][nt][2], s0, b0), 0.f),
                           fmaxf(fmaf(c[mt][nt][3], s1, b1), 0.f) };
            *reinterpret_cast<float2*>(&g_r[(m0+8)*OUT1 + n0]) = v23;
        }
    }
}

// ---------------------------------------------------------------------------
// K3: apply. REWORKED: no divergence, conflict-free LDS.
//   wcs[12][96]: rows 0..5 = w2 group rows, 6..11 = w3 group rows.
//   phase1 items mapped w-fastest -> wcs access is warp-uniform broadcast,
//   rs stride 97 (==1 mod 32) conflict-free.
//   sms padded to 37 floats/row (coprime with 32) -> conflict-free in ph2/ph3.
// ---------------------------------------------------------------------------
__global__ __launch_bounds__(128) void apply_kernel(
    const float* __restrict__ x,
    const float* __restrict__ w2, const float* __restrict__ b2,
    const float* __restrict__ w3, const float* __restrict__ b3,
    float* __restrict__ out)
{
    const int g = blockIdx.x, h2 = blockIdx.y, b = blockIdx.z;
    __shared__ float bufA[GCD*3*3*58];      // 33408 B: rs (5432 fl) then xs
    __shared__ float wcs[12][96];           // 4608 B
    __shared__ float bcs[12];               // 48 B
    __shared__ float wab[WD][12];           // 2688 B
    __shared__ float sms[WD*37];            // 8288 B: [w*37 + t*9 + kk]
    // total 49040 B < 48 KB static limit

    float* rs = bufA;                                            // [WD][97]
    float (*xs)[3][3][58] = reinterpret_cast<float(*)[3][3][58]>(bufA);

    const int tid = threadIdx.x;
    const unsigned posBase = (unsigned)(b*HD + h2)*WD;

    // Phase 0: load r row (coalesced), weights, biases
    for (int idx = tid; idx < WD * OUT1; idx += 128) {
        int w = idx / OUT1, j = idx % OUT1;
        rs[w*97 + j] = g_r[posBase*OUT1 + idx];
    }
    for (int idx = tid; idx < 12 * 96; idx += 128) {
        int q = idx / 96, j = idx % 96;
        wcs[q][j] = (q < 6) ? w2[(g*6 + q)*OUT1 + j]
                            : w3[(g*6 + q - 6)*OUT1 + j];
    }
    if (tid < 12) {
        bcs[tid] = (tid < 6) ? b2[g*6 + tid] : b3[g*6 + tid - 6];
    }
    __syncthreads();

    // Phase 1: matvecs. items = (q, w), w lane-fastest.
    for (int it = tid; it < WD * 12; it += 128) {
        int w = it % WD;
        int q = it / WD;         // warp-uniform except at 56-boundaries
        float acc = bcs[q];
        #pragma unroll 8
        for (int j = 0; j < 96; j++)
            acc = fmaf(wcs[q][j], rs[w*97 + j], acc);   // broadcast x conflict-free
        wab[w][q] = acc;
    }
    __syncthreads();   // rs dead; bufA reused as xs

    // Phase 2a: softmax over kk=9 per (w, nh, nw); pre-divide by 9 (mean)
    for (int it = tid; it < WD * 4; it += 128) {
        int t = it % 4;          // t = nh*2 + nw
        int w = it / 4;
        int nh = t >> 1, nw = t & 1;
        float e[9], m = -1e30f;
        #pragma unroll
        for (int kk = 0; kk < 9; kk++) {
            int kh = kk / 3, kw = kk % 3;
            e[kk] = wab[w][kh*2 + nh] * wab[w][6 + kw*2 + nw];
            m = fmaxf(m, e[kk]);
        }
        float s = 0.f;
        #pragma unroll
        for (int kk = 0; kk < 9; kk++) { e[kk] = expf(e[kk] - m); s += e[kk]; }
        float inv = 1.f / (s * 9.f);
        #pragma unroll
        for (int kk = 0; kk < 9; kk++) sms[w*37 + t*9 + kk] = e[kk] * inv;
    }
    // Phase 2b (same phase): load scrambled taps into xs (overwrites rs)
    load_taps(x, b, g, h2, xs, tid);
    __syncthreads();

    const int jv0 = h2 % 3, jv1 = (56 + h2) % 3, jv2 = (112 + h2) % 3;
    const int jvv[3] = {jv0, jv1, jv2};

    // Phase 3: apply dynamic kernel. items = (gc, w), w lane-fastest.
    for (int it = tid; it < GCD * WD; it += 128) {
        int w  = it % WD;
        int gc = it / WD;
        float o[4] = {0.f, 0.f, 0.f, 0.f};
        #pragma unroll
        for (int kk = 0; kk < 9; kk++) {
            int kh = kk / 3, kw = kk % 3;
            float u = xs[gc][kw][kh][w + jvv[kw]];
            #pragma unroll
            for (int t = 0; t < 4; t++)
                o[t] = fmaf(u, sms[w*37 + t*9 + kk], o[t]);
        }
        int c = g*GCD + gc;
        #pragma unroll
        for (int t = 0; t < 4; t++) {
            int nh = t >> 1, nw = t & 1;
            out[(((unsigned)(b*CD + c))*OWD + 2*h2 + nh)*OWD + 2*w + nw] = o[t];
        }
    }
}

// ---------------------------------------------------------------------------
extern "C" void kernel_launch(void* const* d_in, const int* in_sizes, int n_in,
                              void* d_out, int out_size) {
    const float* x     = (const float*)d_in[0];
    const float* w1    = (const float*)d_in[1];
    const float* gamma = (const float*)d_in[2];
    const float* beta  = (const float*)d_in[3];
    const float* mean  = (const float*)d_in[4];
    const float* var   = (const float*)d_in[5];
    const float* w2    = (const float*)d_in[6];
    const float* b2    = (const float*)d_in[7];
    const float* w3    = (const float*)d_in[8];
    const float* b3    = (const float*)d_in[9];
    float* out = (float*)d_out;

    dim3 gridA(GD, HD, BD);   // (16, 56, 4)
    desc_kernel<<<gridA, 128>>>(x);
    gemm_tc_kernel<<<POSN / GBM, 256>>>(w1, gamma, beta, mean, var);
    apply_kernel<<<gridA, 128>>>(x, w2, b2, w3, b3, out);
}